// round 1
// baseline (speedup 1.0000x reference)
#include <cuda_runtime.h>

#define BATCH 2
#define NSEQ  4096
#define DIMM  512
#define HEADS 8
#define DHEAD 64
#define HALF  2048
#define SCALE 0.04419417382415922f   // 512^-0.5

// Scratch (no cudaMalloc allowed): qkv [8192][1536], attn out [8192][512]
__device__ float g_qkv[(size_t)BATCH * NSEQ * 3 * DIMM];
__device__ float g_att[(size_t)BATCH * NSEQ * DIMM];

// ---------------------------------------------------------------------------
// Tiled SGEMM: C[M,N] = A[M,K] * B[K,N] (+ bias). 128x128 tile, BK=16,
// 256 threads, 8x8 per-thread fragment. M,N,K multiples of tile sizes.
// ---------------------------------------------------------------------------
template <bool BIAS>
__global__ __launch_bounds__(256) void sgemm_kernel(
    const float* __restrict__ A, const float* __restrict__ B,
    const float* __restrict__ bias, float* __restrict__ C,
    int M, int N, int K)
{
    __shared__ float As[16][136];   // A tile transposed: As[k][m]
    __shared__ float Bs[16][128];   // B tile natural:    Bs[k][n]

    const int tid = threadIdx.x;
    const int m0 = blockIdx.y << 7;
    const int n0 = blockIdx.x << 7;
    const int tm = (tid >> 4) << 3;   // 0..120
    const int tn = (tid & 15) << 3;   // 0..120

    const int arow = tid >> 2;          // 0..63
    const int acol = (tid & 3) << 2;    // 0,4,8,12
    const int brow = tid >> 5;          // 0..7
    const int bcol = (tid & 31) << 2;   // 0..124

    float acc[8][8];
#pragma unroll
    for (int i = 0; i < 8; i++)
#pragma unroll
        for (int j = 0; j < 8; j++) acc[i][j] = 0.0f;

    for (int kt = 0; kt < K; kt += 16) {
#pragma unroll
        for (int l = 0; l < 2; l++) {
            float4 v = *(const float4*)(A + (size_t)(m0 + arow + l * 64) * K + kt + acol);
            As[acol + 0][arow + l * 64] = v.x;
            As[acol + 1][arow + l * 64] = v.y;
            As[acol + 2][arow + l * 64] = v.z;
            As[acol + 3][arow + l * 64] = v.w;
        }
#pragma unroll
        for (int l = 0; l < 2; l++) {
            *(float4*)&Bs[brow + l * 8][bcol] =
                *(const float4*)(B + (size_t)(kt + brow + l * 8) * N + n0 + bcol);
        }
        __syncthreads();

#pragma unroll
        for (int kk = 0; kk < 16; kk++) {
            float a[8], b[8];
            *(float4*)(a)     = *(const float4*)&As[kk][tm];
            *(float4*)(a + 4) = *(const float4*)&As[kk][tm + 4];
            *(float4*)(b)     = *(const float4*)&Bs[kk][tn];
            *(float4*)(b + 4) = *(const float4*)&Bs[kk][tn + 4];
#pragma unroll
            for (int i = 0; i < 8; i++)
#pragma unroll
                for (int j = 0; j < 8; j++)
                    acc[i][j] += a[i] * b[j];
        }
        __syncthreads();
    }

#pragma unroll
    for (int i = 0; i < 8; i++) {
        float* crow = C + (size_t)(m0 + tm + i) * N + n0 + tn;
        float4 o0, o1;
        if (BIAS) {
            o0 = make_float4(acc[i][0] + bias[n0 + tn + 0], acc[i][1] + bias[n0 + tn + 1],
                             acc[i][2] + bias[n0 + tn + 2], acc[i][3] + bias[n0 + tn + 3]);
            o1 = make_float4(acc[i][4] + bias[n0 + tn + 4], acc[i][5] + bias[n0 + tn + 5],
                             acc[i][6] + bias[n0 + tn + 6], acc[i][7] + bias[n0 + tn + 7]);
        } else {
            o0 = make_float4(acc[i][0], acc[i][1], acc[i][2], acc[i][3]);
            o1 = make_float4(acc[i][4], acc[i][5], acc[i][6], acc[i][7]);
        }
        *(float4*)(crow)     = o0;
        *(float4*)(crow + 4) = o1;
    }
}

// ---------------------------------------------------------------------------
// Flash attention over k_t. BM=128 query rows per block, BN=64 keys per tile,
// 128 threads, 8x8 fragments. Values come from v_s for first-half queries and
// v_t for second-half queries (per reference).
// Shared: Qt[d][qrow] 64x132, Kt[d][key] 64x68, Vs[key][d] 64x68, Pt[key][qrow] 64x132.
// ---------------------------------------------------------------------------
#define SQT 132
#define SKT 68
#define SVS 68
#define SPT 132
#define ATTN_SMEM ((64 * (SQT + SKT + SVS + SPT)) * sizeof(float))  // 102400 B

__global__ __launch_bounds__(128) void attn_kernel(
    const float* __restrict__ qkv, float* __restrict__ att)
{
    extern __shared__ float smem[];
    float* Qt = smem;
    float* Kt = Qt + 64 * SQT;
    float* Vs = Kt + 64 * SKT;
    float* Pt = Vs + 64 * SVS;

    const int tid = threadIdx.x;
    const int bh = blockIdx.y;
    const int b = bh >> 3, h = bh & 7;
    const int i0 = blockIdx.x << 7;           // query row base (tile of 128)
    const int ty = tid >> 3;                  // 0..15
    const int tx = tid & 7;                   // 0..7
    const int r0 = ty << 3;                   // fragment query rows
    const int c0 = tx << 3;                   // fragment key cols / d cols

    const float* qbase = qkv + ((size_t)(b * NSEQ + i0)) * 1536 + h * 64;
    const float* kbase = qkv + ((size_t)(b * NSEQ + HALF)) * 1536 + 512 + h * 64;
    const int voff = (i0 < HALF) ? 0 : HALF;
    const float* vbase = qkv + ((size_t)(b * NSEQ + voff)) * 1536 + 1024 + h * 64;

    // Load Q tile (128 rows x 64 dims), transposed into Qt[d][row]
#pragma unroll
    for (int l = 0; l < 16; l++) {
        int f = tid + (l << 7);            // 0..2047 float4 index
        int row = f >> 4;                  // 0..127
        int cc = (f & 15) << 2;            // 0..60
        float4 v = *(const float4*)(qbase + (size_t)row * 1536 + cc);
        Qt[(cc + 0) * SQT + row] = v.x;
        Qt[(cc + 1) * SQT + row] = v.y;
        Qt[(cc + 2) * SQT + row] = v.z;
        Qt[(cc + 3) * SQT + row] = v.w;
    }

    float m[8], lsum[8], o[8][8];
#pragma unroll
    for (int r = 0; r < 8; r++) {
        m[r] = -1e30f;
        lsum[r] = 0.0f;
#pragma unroll
        for (int c = 0; c < 8; c++) o[r][c] = 0.0f;
    }

    for (int jt = 0; jt < HALF; jt += 64) {
        // Load K tile transposed (Kt[d][key]) and V tile natural (Vs[key][d])
#pragma unroll
        for (int l = 0; l < 8; l++) {
            int f = tid + (l << 7);        // 0..1023
            int row = f >> 4;              // key 0..63
            int cc = (f & 15) << 2;
            float4 kv = *(const float4*)(kbase + (size_t)(jt + row) * 1536 + cc);
            Kt[(cc + 0) * SKT + row] = kv.x;
            Kt[(cc + 1) * SKT + row] = kv.y;
            Kt[(cc + 2) * SKT + row] = kv.z;
            Kt[(cc + 3) * SKT + row] = kv.w;
            *(float4*)&Vs[row * SVS + cc] =
                *(const float4*)(vbase + (size_t)(jt + row) * 1536 + cc);
        }
        __syncthreads();

        // S = Q K^T (fragment 8x8)
        float s[8][8];
#pragma unroll
        for (int r = 0; r < 8; r++)
#pragma unroll
            for (int c = 0; c < 8; c++) s[r][c] = 0.0f;

#pragma unroll 8
        for (int k = 0; k < 64; k++) {
            float qa[8], kb[8];
            *(float4*)(qa)     = *(const float4*)&Qt[k * SQT + r0];
            *(float4*)(qa + 4) = *(const float4*)&Qt[k * SQT + r0 + 4];
            *(float4*)(kb)     = *(const float4*)&Kt[k * SKT + c0];
            *(float4*)(kb + 4) = *(const float4*)&Kt[k * SKT + c0 + 4];
#pragma unroll
            for (int r = 0; r < 8; r++)
#pragma unroll
                for (int c = 0; c < 8; c++)
                    s[r][c] += qa[r] * kb[c];
        }

        // Online softmax (rows split across tx: 8 lanes hold 8 cols each)
#pragma unroll
        for (int r = 0; r < 8; r++) {
            float mx = -1e30f;
#pragma unroll
            for (int c = 0; c < 8; c++) {
                s[r][c] *= SCALE;
                mx = fmaxf(mx, s[r][c]);
            }
            mx = fmaxf(mx, __shfl_xor_sync(0xffffffffu, mx, 1));
            mx = fmaxf(mx, __shfl_xor_sync(0xffffffffu, mx, 2));
            mx = fmaxf(mx, __shfl_xor_sync(0xffffffffu, mx, 4));
            float mn = fmaxf(m[r], mx);
            float corr = __expf(m[r] - mn);
            m[r] = mn;
            float ps = 0.0f;
#pragma unroll
            for (int c = 0; c < 8; c++) {
                float p = __expf(s[r][c] - mn);
                s[r][c] = p;
                ps += p;
            }
            ps += __shfl_xor_sync(0xffffffffu, ps, 1);
            ps += __shfl_xor_sync(0xffffffffu, ps, 2);
            ps += __shfl_xor_sync(0xffffffffu, ps, 4);
            lsum[r] = lsum[r] * corr + ps;
#pragma unroll
            for (int c = 0; c < 8; c++) o[r][c] *= corr;
        }

        // Write P transposed: Pt[key][qrow]
#pragma unroll
        for (int c = 0; c < 8; c++) {
            float4 p0 = make_float4(s[0][c], s[1][c], s[2][c], s[3][c]);
            float4 p1 = make_float4(s[4][c], s[5][c], s[6][c], s[7][c]);
            *(float4*)&Pt[(c0 + c) * SPT + r0]     = p0;
            *(float4*)&Pt[(c0 + c) * SPT + r0 + 4] = p1;
        }
        __syncthreads();

        // O += P V  (fragment 8x8: rows = q rows, cols = d dims)
#pragma unroll 8
        for (int j = 0; j < 64; j++) {
            float pa[8], vb[8];
            *(float4*)(pa)     = *(const float4*)&Pt[j * SPT + r0];
            *(float4*)(pa + 4) = *(const float4*)&Pt[j * SPT + r0 + 4];
            *(float4*)(vb)     = *(const float4*)&Vs[j * SVS + c0];
            *(float4*)(vb + 4) = *(const float4*)&Vs[j * SVS + c0 + 4];
#pragma unroll
            for (int r = 0; r < 8; r++)
#pragma unroll
                for (int c = 0; c < 8; c++)
                    o[r][c] += pa[r] * vb[c];
        }
        __syncthreads();
    }

    // Epilogue: normalize and write to attention scratch [8192][512]
    float* obase = att + ((size_t)(b * NSEQ + i0 + r0)) * 512 + h * 64 + c0;
#pragma unroll
    for (int r = 0; r < 8; r++) {
        float inv = 1.0f / lsum[r];
        float4 w0 = make_float4(o[r][0] * inv, o[r][1] * inv, o[r][2] * inv, o[r][3] * inv);
        float4 w1 = make_float4(o[r][4] * inv, o[r][5] * inv, o[r][6] * inv, o[r][7] * inv);
        *(float4*)(obase + (size_t)r * 512)     = w0;
        *(float4*)(obase + (size_t)r * 512 + 4) = w1;
    }
}

// ---------------------------------------------------------------------------
extern "C" void kernel_launch(void* const* d_in, const int* in_sizes, int n_in,
                              void* d_out, int out_size)
{
    const float* x    = (const float*)d_in[0];   // [2,4096,512]
    const float* Wqkv = (const float*)d_in[1];   // [512,1536]
    const float* Wout = (const float*)d_in[2];   // [512,512]
    const float* bout = (const float*)d_in[3];   // [512]
    float* out = (float*)d_out;                  // [2,4096,512]

    void* qkv_ptr = nullptr;
    void* att_ptr = nullptr;
    cudaGetSymbolAddress(&qkv_ptr, g_qkv);
    cudaGetSymbolAddress(&att_ptr, g_att);
    float* qkv = (float*)qkv_ptr;
    float* att = (float*)att_ptr;

    const int M = BATCH * NSEQ;   // 8192

    // 1) qkv = x @ Wqkv  : [8192,512] x [512,1536]
    {
        dim3 grid(3 * DIMM / 128, M / 128);
        sgemm_kernel<false><<<grid, 256>>>(x, Wqkv, nullptr, qkv, M, 3 * DIMM, DIMM);
    }

    // 2) fused flash attention -> att [8192,512]
    {
        cudaFuncSetAttribute(attn_kernel, cudaFuncAttributeMaxDynamicSharedMemorySize,
                             (int)ATTN_SMEM);
        dim3 grid(NSEQ / 128, BATCH * HEADS);
        attn_kernel<<<grid, 128, ATTN_SMEM>>>(qkv, att);
    }

    // 3) out = att @ Wout + b_out : [8192,512] x [512,512]
    {
        dim3 grid(DIMM / 128, M / 128);
        sgemm_kernel<true><<<grid, 256>>>(att, Wout, bout, out, M, DIMM, DIMM);
    }
}

// round 3
// speedup vs baseline: 2.7106x; 2.7106x over previous
#include <cuda_runtime.h>
#include <cstdint>

#define BATCH 2
#define NSEQ  4096
#define DIMM  512
#define HEADS 8
#define DHEAD 64
#define HALF  2048
#define SCALE      0.04419417382415922f            // 512^-0.5
#define SCALE_L2E  0.06377887559289643f            // SCALE * log2(e)

// Scratch (no cudaMalloc allowed)
__device__ float g_qkv[(size_t)BATCH * NSEQ * 3 * DIMM];   // [8192][1536]
__device__ float g_att[(size_t)BATCH * NSEQ * DIMM];       // [8192][512]

// ============================================================================
// helpers
// ============================================================================
__device__ __forceinline__ uint32_t f32_to_tf32(float f) {
    uint32_t r;
    asm("cvt.rna.tf32.f32 %0, %1;" : "=r"(r) : "f"(f));
    return r;
}

__device__ __forceinline__ uint4 cvt4(float4 v) {
    uint4 u;
    u.x = f32_to_tf32(v.x); u.y = f32_to_tf32(v.y);
    u.z = f32_to_tf32(v.z); u.w = f32_to_tf32(v.w);
    return u;
}

__device__ __forceinline__ float ex2(float x) {
    float y;
    asm("ex2.approx.f32 %0, %1;" : "=f"(y) : "f"(x));
    return y;
}

// D += A*B, m16n8k8 tf32. a: 4 regs, b: 2 regs, d: 4 f32 (in/out).
__device__ __forceinline__ void mma8(float* d, const uint32_t* a, const uint32_t* b) {
    asm volatile(
        "mma.sync.aligned.m16n8k8.row.col.f32.tf32.tf32.f32 "
        "{%0,%1,%2,%3}, {%4,%5,%6,%7}, {%8,%9}, {%0,%1,%2,%3};"
        : "+f"(d[0]), "+f"(d[1]), "+f"(d[2]), "+f"(d[3])
        : "r"(a[0]), "r"(a[1]), "r"(a[2]), "r"(a[3]), "r"(b[0]), "r"(b[1]));
}

// ============================================================================
// MMA GEMM: C[M,N] = A[M,K] @ B[K,N] (+bias). CTA tile 128x128, BK=16,
// 8 warps (4 m x 2 n), each warp 32x64. Register prefetch double-buffer.
// ============================================================================
template <bool BIAS>
__global__ __launch_bounds__(256) void tc_gemm(
    const float* __restrict__ A, const float* __restrict__ B,
    const float* __restrict__ bias, float* __restrict__ C,
    int M, int N, int K)
{
    __shared__ __align__(16) uint32_t As[128 * 20];   // [m][k] pad 20
    __shared__ __align__(16) uint32_t Bs[16 * 132];   // [k][n] pad 132

    const int tid = threadIdx.x;
    const int wid = tid >> 5, lane = tid & 31;
    const int g = lane >> 2, t = lane & 3;
    const int wm = wid & 3, wn = wid >> 2;
    const int m0 = blockIdx.y << 7, n0 = blockIdx.x << 7;

    const int ar = tid >> 2, ac = (tid & 3) << 2;   // A tile: 64 rows x 16 cols per pass
    const int br = tid >> 5, bc = (tid & 31) << 2;  // B tile: 8 rows x 128 cols per pass

    float acc[2][8][4];
#pragma unroll
    for (int mt = 0; mt < 2; mt++)
#pragma unroll
        for (int nt = 0; nt < 8; nt++)
#pragma unroll
            for (int q = 0; q < 4; q++) acc[mt][nt][q] = 0.0f;

    float4 pa0, pa1, pb0, pb1;
    pa0 = *(const float4*)(A + (size_t)(m0 + ar) * K + ac);
    pa1 = *(const float4*)(A + (size_t)(m0 + ar + 64) * K + ac);
    pb0 = *(const float4*)(B + (size_t)br * N + n0 + bc);
    pb1 = *(const float4*)(B + (size_t)(br + 8) * N + n0 + bc);

    const int NT = K >> 4;
    for (int kt = 0; kt < NT; kt++) {
        *(uint4*)&As[(ar)      * 20 + ac] = cvt4(pa0);
        *(uint4*)&As[(ar + 64) * 20 + ac] = cvt4(pa1);
        *(uint4*)&Bs[(br)     * 132 + bc] = cvt4(pb0);
        *(uint4*)&Bs[(br + 8) * 132 + bc] = cvt4(pb1);
        __syncthreads();

        if (kt + 1 < NT) {
            const int ko = (kt + 1) << 4;
            pa0 = *(const float4*)(A + (size_t)(m0 + ar) * K + ko + ac);
            pa1 = *(const float4*)(A + (size_t)(m0 + ar + 64) * K + ko + ac);
            pb0 = *(const float4*)(B + (size_t)(ko + br) * N + n0 + bc);
            pb1 = *(const float4*)(B + (size_t)(ko + br + 8) * N + n0 + bc);
        }

#pragma unroll
        for (int ks = 0; ks < 2; ks++) {
            const int kb = ks << 3;
            uint32_t af[2][4];
#pragma unroll
            for (int mt = 0; mt < 2; mt++) {
                const int r = (wm << 5) + (mt << 4);
                af[mt][0] = As[(r + g)     * 20 + kb + t];
                af[mt][1] = As[(r + g + 8) * 20 + kb + t];
                af[mt][2] = As[(r + g)     * 20 + kb + t + 4];
                af[mt][3] = As[(r + g + 8) * 20 + kb + t + 4];
            }
#pragma unroll
            for (int nt = 0; nt < 8; nt++) {
                uint32_t bf[2];
                const int c = (wn << 6) + (nt << 3);
                bf[0] = Bs[(kb + t)     * 132 + c + g];
                bf[1] = Bs[(kb + t + 4) * 132 + c + g];
                mma8(acc[0][nt], af[0], bf);
                mma8(acc[1][nt], af[1], bf);
            }
        }
        __syncthreads();
    }

#pragma unroll
    for (int mt = 0; mt < 2; mt++) {
#pragma unroll
        for (int nt = 0; nt < 8; nt++) {
            const int row = m0 + (wm << 5) + (mt << 4) + g;
            const int col = n0 + (wn << 6) + (nt << 3) + (t << 1);
            float b0 = 0.f, b1 = 0.f;
            if (BIAS) { b0 = bias[col]; b1 = bias[col + 1]; }
            float2 v0 = make_float2(acc[mt][nt][0] + b0, acc[mt][nt][1] + b1);
            float2 v1 = make_float2(acc[mt][nt][2] + b0, acc[mt][nt][3] + b1);
            *(float2*)(C + (size_t)row * N + col)       = v0;
            *(float2*)(C + (size_t)(row + 8) * N + col) = v1;
        }
    }
}

// ============================================================================
// Flash attention with mma.sync tf32. 128 q-rows per CTA, 4 warps (32 rows
// each), 64-key tiles, online softmax in exp2 domain.
// Smem (tf32 bits): Qs[128][68], Kt[64][68], Vs[64][68], Ps[128][68]
// ============================================================================
#define ATT_QS 0
#define ATT_KT 8704
#define ATT_VS 13056
#define ATT_PS 17408
#define ATT_WORDS 26112
#define ATT_SMEM (ATT_WORDS * 4)

__global__ __launch_bounds__(128) void attn_kernel(
    const float* __restrict__ qkv, float* __restrict__ att)
{
    extern __shared__ __align__(16) uint32_t sm[];
    uint32_t* Qs = sm + ATT_QS;
    uint32_t* Kt = sm + ATT_KT;
    uint32_t* Vs = sm + ATT_VS;
    uint32_t* Ps = sm + ATT_PS;

    const int tid = threadIdx.x;
    const int w = tid >> 5, lane = tid & 31;
    const int g = lane >> 2, t = lane & 3;
    const int bh = blockIdx.y, b = bh >> 3, h = bh & 7;
    const int i0 = blockIdx.x << 7;
    const int qr = w << 5;                       // warp's q-row base in tile

    const float* qbase = qkv + (size_t)(b * NSEQ + i0) * 1536 + h * 64;
    const float* kbase = qkv + (size_t)(b * NSEQ + HALF) * 1536 + 512 + h * 64;
    const float* vbase = qkv + (size_t)(b * NSEQ + ((i0 < HALF) ? 0 : HALF)) * 1536
                             + 1024 + h * 64;

    // Q tile -> Qs[q][d] (tf32)
#pragma unroll
    for (int l = 0; l < 16; l++) {
        int f = tid + (l << 7);
        int row = f >> 4, cq = (f & 15) << 2;
        float4 v = *(const float4*)(qbase + (size_t)row * 1536 + cq);
        *(uint4*)&Qs[row * 68 + cq] = cvt4(v);
    }

    float mx[4], ls[4];
#pragma unroll
    for (int i = 0; i < 4; i++) { mx[i] = -1e30f; ls[i] = 0.0f; }
    float o[2][8][4];
#pragma unroll
    for (int mt = 0; mt < 2; mt++)
#pragma unroll
        for (int nt = 0; nt < 8; nt++)
#pragma unroll
            for (int q = 0; q < 4; q++) o[mt][nt][q] = 0.0f;

    for (int jt = 0; jt < 32; jt++) {
        __syncthreads();   // prior PV readers done before overwrite
        const float* kg = kbase + (size_t)(jt << 6) * 1536;
        const float* vg = vbase + (size_t)(jt << 6) * 1536;
#pragma unroll
        for (int l = 0; l < 8; l++) {
            int f = tid + (l << 7);
            int row = f >> 4, cq = (f & 15) << 2;
            float4 kv = *(const float4*)(kg + (size_t)row * 1536 + cq);
            Kt[(cq + 0) * 68 + row] = f32_to_tf32(kv.x);
            Kt[(cq + 1) * 68 + row] = f32_to_tf32(kv.y);
            Kt[(cq + 2) * 68 + row] = f32_to_tf32(kv.z);
            Kt[(cq + 3) * 68 + row] = f32_to_tf32(kv.w);
            float4 vv = *(const float4*)(vg + (size_t)row * 1536 + cq);
            *(uint4*)&Vs[row * 68 + cq] = cvt4(vv);
        }
        __syncthreads();

        // ---- S = Q K^T ----
        float s[2][8][4];
#pragma unroll
        for (int mt = 0; mt < 2; mt++)
#pragma unroll
            for (int nt = 0; nt < 8; nt++)
#pragma unroll
                for (int q = 0; q < 4; q++) s[mt][nt][q] = 0.0f;

#pragma unroll
        for (int kb = 0; kb < 64; kb += 8) {
            uint32_t af[2][4];
#pragma unroll
            for (int mt = 0; mt < 2; mt++) {
                const int r = qr + (mt << 4);
                af[mt][0] = Qs[(r + g)     * 68 + kb + t];
                af[mt][1] = Qs[(r + g + 8) * 68 + kb + t];
                af[mt][2] = Qs[(r + g)     * 68 + kb + t + 4];
                af[mt][3] = Qs[(r + g + 8) * 68 + kb + t + 4];
            }
#pragma unroll
            for (int nt = 0; nt < 8; nt++) {
                uint32_t bf[2];
                bf[0] = Kt[(kb + t)     * 68 + (nt << 3) + g];
                bf[1] = Kt[(kb + t + 4) * 68 + (nt << 3) + g];
                mma8(s[0][nt], af[0], bf);
                mma8(s[1][nt], af[1], bf);
            }
        }

        // ---- online softmax (exp2 domain) ----
#pragma unroll
        for (int mt = 0; mt < 2; mt++) {
#pragma unroll
            for (int hf = 0; hf < 2; hf++) {
                const int si = mt * 2 + hf;
                const int e0 = hf << 1, e1 = e0 + 1;
                float rm = -1e30f;
#pragma unroll
                for (int nt = 0; nt < 8; nt++) {
                    s[mt][nt][e0] *= SCALE_L2E;
                    s[mt][nt][e1] *= SCALE_L2E;
                    rm = fmaxf(rm, fmaxf(s[mt][nt][e0], s[mt][nt][e1]));
                }
                rm = fmaxf(rm, __shfl_xor_sync(0xffffffffu, rm, 1));
                rm = fmaxf(rm, __shfl_xor_sync(0xffffffffu, rm, 2));
                const float mn = fmaxf(mx[si], rm);
                const float corr = ex2(mx[si] - mn);
                mx[si] = mn;
                float ps = 0.0f;
                const int prow = qr + (mt << 4) + (hf << 3) + g;
#pragma unroll
                for (int nt = 0; nt < 8; nt++) {
                    float p0 = ex2(s[mt][nt][e0] - mn);
                    float p1 = ex2(s[mt][nt][e1] - mn);
                    ps += p0 + p1;
                    uint2 u;
                    u.x = f32_to_tf32(p0);
                    u.y = f32_to_tf32(p1);
                    *(uint2*)&Ps[prow * 68 + (nt << 3) + (t << 1)] = u;
                }
                ps += __shfl_xor_sync(0xffffffffu, ps, 1);
                ps += __shfl_xor_sync(0xffffffffu, ps, 2);
                ls[si] = ls[si] * corr + ps;
#pragma unroll
                for (int nt = 0; nt < 8; nt++) {
                    o[mt][nt][e0] *= corr;
                    o[mt][nt][e1] *= corr;
                }
            }
        }
        __syncwarp();   // Ps is warp-private; make it visible within warp

        // ---- O += P V ----
#pragma unroll
        for (int kb = 0; kb < 64; kb += 8) {
            uint32_t af[2][4];
#pragma unroll
            for (int mt = 0; mt < 2; mt++) {
                const int r = qr + (mt << 4);
                af[mt][0] = Ps[(r + g)     * 68 + kb + t];
                af[mt][1] = Ps[(r + g + 8) * 68 + kb + t];
                af[mt][2] = Ps[(r + g)     * 68 + kb + t + 4];
                af[mt][3] = Ps[(r + g + 8) * 68 + kb + t + 4];
            }
#pragma unroll
            for (int nt = 0; nt < 8; nt++) {
                uint32_t bf[2];
                bf[0] = Vs[(kb + t)     * 68 + (nt << 3) + g];
                bf[1] = Vs[(kb + t + 4) * 68 + (nt << 3) + g];
                mma8(o[0][nt], af[0], bf);
                mma8(o[1][nt], af[1], bf);
            }
        }
    }

    // epilogue: normalize, write [8192][512]
#pragma unroll
    for (int mt = 0; mt < 2; mt++) {
#pragma unroll
        for (int hf = 0; hf < 2; hf++) {
            const int si = mt * 2 + hf;
            const float inv = 1.0f / ls[si];
            const int e0 = hf << 1, e1 = e0 + 1;
            const int row = i0 + qr + (mt << 4) + (hf << 3) + g;
            float* ob = att + (size_t)(b * NSEQ + row) * 512 + h * 64 + (t << 1);
#pragma unroll
            for (int nt = 0; nt < 8; nt++) {
                float2 v = make_float2(o[mt][nt][e0] * inv, o[mt][nt][e1] * inv);
                *(float2*)(ob + (nt << 3)) = v;
            }
        }
    }
}

// ============================================================================
extern "C" void kernel_launch(void* const* d_in, const int* in_sizes, int n_in,
                              void* d_out, int out_size)
{
    const float* x    = (const float*)d_in[0];   // [2,4096,512]
    const float* Wqkv = (const float*)d_in[1];   // [512,1536]
    const float* Wout = (const float*)d_in[2];   // [512,512]
    const float* bout = (const float*)d_in[3];   // [512]
    float* out = (float*)d_out;                  // [2,4096,512]

    void *qkv_ptr, *att_ptr;
    cudaGetSymbolAddress(&qkv_ptr, g_qkv);
    cudaGetSymbolAddress(&att_ptr, g_att);
    float* qkv = (float*)qkv_ptr;
    float* att = (float*)att_ptr;

    const int M = BATCH * NSEQ;   // 8192

    cudaFuncSetAttribute(attn_kernel, cudaFuncAttributeMaxDynamicSharedMemorySize,
                         ATT_SMEM);

    // 1) qkv = x @ Wqkv
    tc_gemm<false><<<dim3((3 * DIMM) / 128, M / 128), 256>>>(
        x, Wqkv, nullptr, qkv, M, 3 * DIMM, DIMM);

    // 2) flash attention -> att
    attn_kernel<<<dim3(NSEQ / 128, BATCH * HEADS), 128, ATT_SMEM>>>(qkv, att);

    // 3) out = att @ Wout + b_out
    tc_gemm<true><<<dim3(DIMM / 128, M / 128), 256>>>(
        att, Wout, bout, out, M, DIMM, DIMM);
}